// round 15
// baseline (speedup 1.0000x reference)
#include <cuda_runtime.h>
#include <math_constants.h>

#define B_      8
#define H_      8
#define T_      8192
#define DH      64
#define BUCKETS 128
#define BSZ     64
#define BH      64
#define HH      4

// scratch (device globals; no allocation allowed)
__device__ float g_bucket_sum[BH * BUCKETS * DH];   // 2 MB
__device__ float g_feat[BH * BUCKETS * 2 * DH];     // 4 MB
__device__ int   g_ridx[BH * BUCKETS];
__device__ float g_rw[BH * BUCKETS];

typedef unsigned long long u64;

__device__ __forceinline__ void fma2(u64 &d, u64 a, u64 b) {
    asm("fma.rn.f32x2 %0, %1, %2, %0;" : "+l"(d) : "l"(a), "l"(b));
}
__device__ __forceinline__ float f2sum(u64 v) {
    return __uint_as_float((unsigned)v) + __uint_as_float((unsigned)(v >> 32));
}

// ---------------------------------------------------------------------------
// Kernel 1: per-bucket sums of rotated K + first-token capture (exact R8)
__global__ void k_bucket_sums(const float* __restrict__ k) {
    int u = blockIdx.x, f = blockIdx.y;
    int h = f & 7; bool rot = (h >= HH);
    const float* kg = k + (size_t)f * T_ * DH;
    __shared__ float4 red[16][17];
    int cgrp = threadIdx.x & 15;
    int c4 = cgrp * 4;
    int rp = threadIdx.x >> 4;

    float4 s = {0.f, 0.f, 0.f, 0.f};
    #pragma unroll
    for (int st = 0; st < 4; st++) {
        int i = rp + 16 * st;
        int tt = u * BSZ + i;
        int src = rot ? ((tt + 63) & (T_ - 1)) : tt;
        float4 vv = *(const float4*)(kg + src * DH + c4);
        s.x += vv.x; s.y += vv.y; s.z += vv.z; s.w += vv.w;
        if (rp == 0 && st == 0)
            *(float4*)&g_feat[(f * BUCKETS + u) * 128 + 64 + c4] = vv;
    }
    red[rp][cgrp] = s;
    __syncthreads();
    if (rp == 0) {
        float4 acc = red[0][cgrp];
        #pragma unroll
        for (int r = 1; r < 16; r++) {
            float4 t2 = red[r][cgrp];
            acc.x += t2.x; acc.y += t2.y; acc.z += t2.z; acc.w += t2.w;
        }
        *(float4*)&g_bucket_sum[(f * BUCKETS + u) * DH + c4] = acc;
    }
}

// ---------------------------------------------------------------------------
// Kernel 2: smem Hillis–Steele scan over buckets -> cumavg feature (exact R8)
__global__ void k_prefix() {
    __shared__ float s[BUCKETS * DH];   // 32 KB
    int f = blockIdx.x, tid = threadIdx.x;
    const float* src = g_bucket_sum + (size_t)f * BUCKETS * DH;

    for (int i = tid; i < BUCKETS * DH / 4; i += 256)
        ((float4*)s)[i] = ((const float4*)src)[i];
    __syncthreads();

    #pragma unroll
    for (int off = 1; off < BUCKETS; off <<= 1) {
        float vals[32];
        #pragma unroll
        for (int t = 0; t < 32; t++) {
            int e = tid + 256 * t;
            int u = e >> 6;
            vals[t] = (u >= off) ? s[e - off * DH] : 0.f;
        }
        __syncthreads();
        #pragma unroll
        for (int t = 0; t < 32; t++) s[tid + 256 * t] += vals[t];
        __syncthreads();
    }

    for (int e = tid; e < BUCKETS * DH; e += 256) {
        int u = e >> 6, d = e & 63;
        float excl = s[e] - src[e];
        float first = g_feat[(f * BUCKETS + u) * 128 + 64 + d];
        g_feat[(f * BUCKETS + u) * 128 + d] = (excl + first) / (float)(u * BSZ + 1);
    }
}

// ---------------------------------------------------------------------------
// Kernel 3: routing v3 — grid (2, BH): block x handles rows [64x, 64x+64)
// SINGLE pass (no unrolled p-loop -> no accumulator duplication/spill).
// Block x=0 stages only 64 W^T cols (causality), x=1 stages 128.
#define RW_STR 130
__global__ void __launch_bounds__(256) k_route(const float* __restrict__ W) {
    extern __shared__ float rsm[];
    float* Xs  = rsm;                    // [64][130]   rows of this block
    float* Wts = rsm + 64 * RW_STR;      // [ncols][130] Wt[c][d] = W[h][d][c]
    int xblk = blockIdx.x;               // 0 or 1
    int f = blockIdx.y, tid = threadIdx.x;
    int h = f & 7;
    int rbase = xblk * 64;
    int ncols = rbase + 64;              // 64 or 128 (power of two)
    int cshift = (xblk == 0) ? 6 : 7;

    // load X rows rbase..rbase+63 (coalesced float4 gmem, float2 smem stores)
    for (int idx = tid; idx < 64 * 32; idx += 256) {
        int u = idx >> 5, d4 = (idx & 31) << 2;
        float4 xv = *(const float4*)&g_feat[(f * BUCKETS + rbase + u) * 128 + d4];
        *(float2*)&Xs[u * RW_STR + d4]     = make_float2(xv.x, xv.y);
        *(float2*)&Xs[u * RW_STR + d4 + 2] = make_float2(xv.z, xv.w);
    }
    // load W[h] transposed, cols [0, ncols) (gmem coalesced along c)
    const float* wh = W + h * 128 * 129;
    for (int idx = tid; idx < (ncols << 7); idx += 256) {
        int d = idx >> cshift, c = idx & (ncols - 1);
        Wts[c * RW_STR + d] = wh[d * 129 + c];
    }
    __syncthreads();

    int wrp = tid >> 5, cg = tid & 31;
    int r0 = rbase + wrp * 8;            // this warp's 8 rows
    int g = ((r0 + 7) >> 5) + 1;         // col groups needed (1..4)

    u64 acc[8][4];
    #pragma unroll
    for (int i = 0; i < 8; i++)
        #pragma unroll
        for (int j = 0; j < 4; j++) acc[i][j] = 0ull;

    #pragma unroll 2
    for (int kk = 0; kk < 128; kk += 2) {
        u64 a2[8];
        #pragma unroll
        for (int i = 0; i < 8; i++)
            a2[i] = *(const u64*)&Xs[(wrp * 8 + i) * RW_STR + kk];
        #pragma unroll 1
        for (int j = 0; j < g; j++) {
            u64 b2 = *(const u64*)&Wts[(cg + 32 * j) * RW_STR + kk];
            #pragma unroll
            for (int i = 0; i < 8; i++) fma2(acc[i][j], a2[i], b2);
        }
    }

    // per-row: leaky_relu, masked softmax over c<=r, top-1 over c<r
    #pragma unroll 1
    for (int i = 0; i < 8; i++) {
        int r = r0 + i;
        float vals[4];
        float m = -CUDART_INF_F;
        #pragma unroll
        for (int j = 0; j < 4; j++) {
            int c = cg + 32 * j;
            float v = f2sum(acc[i][j]);
            v = v > 0.f ? v : 0.01f * v;      // leaky_relu
            vals[j] = v;
            if (j < g && c <= r) m = fmaxf(m, v);
        }
        #pragma unroll
        for (int o = 16; o; o >>= 1) m = fmaxf(m, __shfl_xor_sync(~0u, m, o));
        float sum = 0.f, best = -CUDART_INF_F; int bi = 0x7fffffff;
        #pragma unroll
        for (int j = 0; j < 4; j++) {
            int c = cg + 32 * j;
            if (j < g && c <= r) sum += __expf(vals[j] - m);
            if (j < g && c <  r && vals[j] > best) { best = vals[j]; bi = c; }
        }
        #pragma unroll
        for (int o = 16; o; o >>= 1) {
            sum += __shfl_xor_sync(~0u, sum, o);
            float ob = __shfl_xor_sync(~0u, best, o);
            int   oi = __shfl_xor_sync(~0u, bi, o);
            if (ob > best || (ob == best && oi < bi)) { best = ob; bi = oi; }
        }
        if (cg == 0) {
            if (r == 0) { g_ridx[f * BUCKETS] = 0; g_rw[f * BUCKETS] = 0.f; }
            else {
                g_ridx[f * BUCKETS + r] = bi;                      // 0 = null bucket
                g_rw[f * BUCKETS + r]   = __expf(best - m) / sum;  // softmax weight
            }
        }
    }
}

// ---------------------------------------------------------------------------
// Kernel 4: fused attention tile (exact R8 version — best known: 463.7us)
#define QS_STRIDE  66
#define PS_STRIDE  130
__global__ void __launch_bounds__(256, 2) k_attn(
    const float* __restrict__ q, const float* __restrict__ k, const float* __restrict__ v,
    const float* __restrict__ nullk, const float* __restrict__ nullv,
    float* __restrict__ out)
{
    extern __shared__ float sm[];
    float* Qs  = sm;                                   // [64][66]
    float* K2s = sm + 64 * QS_STRIDE;                  // [128][66]
    float* Ps  = sm;                                   // [64][130] overlay (after sync)
    float* V2T = sm + (64 + 128) * QS_STRIDE;          // [64][130]  V2T[c][j]

    int u = blockIdx.x, f = blockIdx.y, tid = threadIdx.x;
    int h = f & 7; bool rot = (h >= HH);
    const float* qg = q + (size_t)f * T_ * DH;
    const float* kg = k + (size_t)f * T_ * DH;
    const float* vg = v + (size_t)f * T_ * DH;
    int   ridx = g_ridx[f * BUCKETS + u];
    float w    = g_rw[f * BUCKETS + u];

    // ---- load Q, K2 (routed|own), V2T (routed|own transposed) ----
    for (int idx = tid; idx < 64 * 16; idx += 256) {
        int row = idx >> 4, c4 = (idx & 15) << 2;
        int tt  = u * BSZ + row;
        int src = rot ? ((tt + 63) & (T_ - 1)) : tt;
        float4 qv = *(const float4*)(qg + src * DH + c4);
        *(float2*)&Qs[row * QS_STRIDE + c4]     = make_float2(qv.x, qv.y);
        *(float2*)&Qs[row * QS_STRIDE + c4 + 2] = make_float2(qv.z, qv.w);
        float4 kv = *(const float4*)(kg + src * DH + c4);
        *(float2*)&K2s[(64 + row) * QS_STRIDE + c4]     = make_float2(kv.x, kv.y);
        *(float2*)&K2s[(64 + row) * QS_STRIDE + c4 + 2] = make_float2(kv.z, kv.w);
        float4 vv = *(const float4*)(vg + src * DH + c4);
        V2T[(c4 + 0) * PS_STRIDE + 64 + row] = vv.x;
        V2T[(c4 + 1) * PS_STRIDE + 64 + row] = vv.y;
        V2T[(c4 + 2) * PS_STRIDE + 64 + row] = vv.z;
        V2T[(c4 + 3) * PS_STRIDE + 64 + row] = vv.w;
        float4 rk, rv;
        if (ridx == 0) {
            rk = *(const float4*)(nullk + h * DH + c4);
            rv = *(const float4*)(nullv + h * DH + c4);
        } else {
            int st = (ridx - 1) * BSZ + row;
            int s2 = rot ? ((st + 63) & (T_ - 1)) : st;
            rk = *(const float4*)(kg + s2 * DH + c4);
            rv = *(const float4*)(vg + s2 * DH + c4);
        }
        rk.x *= w; rk.y *= w; rk.z *= w; rk.w *= w;
        *(float2*)&K2s[row * QS_STRIDE + c4]     = make_float2(rk.x, rk.y);
        *(float2*)&K2s[row * QS_STRIDE + c4 + 2] = make_float2(rk.z, rk.w);
        V2T[(c4 + 0) * PS_STRIDE + row] = rv.x * w;
        V2T[(c4 + 1) * PS_STRIDE + row] = rv.y * w;
        V2T[(c4 + 2) * PS_STRIDE + row] = rv.z * w;
        V2T[(c4 + 3) * PS_STRIDE + row] = rv.w * w;
    }
    __syncthreads();

    // ---- S = Q @ K2^T with causal col-group skip ----
    int rg = tid >> 5, cg = tid & 31;
    u64 acc[8][4];
    #pragma unroll
    for (int i = 0; i < 8; i++)
        #pragma unroll
        for (int j = 0; j < 4; j++) acc[i][j] = 0ull;

    if (rg >= 4) {
        #pragma unroll 2
        for (int kk = 0; kk < 64; kk += 2) {
            u64 a2[8], b2[4];
            #pragma unroll
            for (int i = 0; i < 8; i++) a2[i] = *(const u64*)&Qs[(rg * 8 + i) * QS_STRIDE + kk];
            #pragma unroll
            for (int j = 0; j < 4; j++) b2[j] = *(const u64*)&K2s[(cg + 32 * j) * QS_STRIDE + kk];
            #pragma unroll
            for (int i = 0; i < 8; i++)
                #pragma unroll
                for (int j = 0; j < 4; j++) fma2(acc[i][j], a2[i], b2[j]);
        }
    } else {
        #pragma unroll 2
        for (int kk = 0; kk < 64; kk += 2) {
            u64 a2[8], b2[3];
            #pragma unroll
            for (int i = 0; i < 8; i++) a2[i] = *(const u64*)&Qs[(rg * 8 + i) * QS_STRIDE + kk];
            #pragma unroll
            for (int j = 0; j < 3; j++) b2[j] = *(const u64*)&K2s[(cg + 32 * j) * QS_STRIDE + kk];
            #pragma unroll
            for (int i = 0; i < 8; i++)
                #pragma unroll
                for (int j = 0; j < 3; j++) fma2(acc[i][j], a2[i], b2[j]);
        }
    }
    __syncthreads();  // all Qs/K2s reads done; Ps overlays them

    {
        const float scale = 0.044194173824159216f;  // 512^-0.5
        #pragma unroll
        for (int i = 0; i < 8; i++)
            #pragma unroll
            for (int j = 0; j < 3; j++)
                Ps[(rg * 8 + i) * PS_STRIDE + (cg + 32 * j)] = f2sum(acc[i][j]) * scale;
        if (rg >= 4) {
            #pragma unroll
            for (int i = 0; i < 8; i++)
                Ps[(rg * 8 + i) * PS_STRIDE + (cg + 96)] = f2sum(acc[i][3]) * scale;
        }
    }
    __syncthreads();

    // ---- masked softmax: warp per 8 rows ----
    {
        int warp = tid >> 5, lane = tid & 31;
        for (int rr = 0; rr < 8; rr++) {
            int r = warp * 8 + rr;
            bool special = rot && (u == BUCKETS - 1) && (r >= 1);
            float vals[4]; bool al[4];
            #pragma unroll
            for (int s = 0; s < 4; s++) {
                int j = lane + 32 * s;
                vals[s] = Ps[r * PS_STRIDE + j];
                bool a = (j < 64) ? true : ((j - 64) <= r);
                if (special && j <= 64) a = false;
                al[s] = a;
            }
            float m = -CUDART_INF_F;
            #pragma unroll
            for (int s = 0; s < 4; s++) if (al[s]) m = fmaxf(m, vals[s]);
            #pragma unroll
            for (int o = 16; o; o >>= 1) m = fmaxf(m, __shfl_xor_sync(~0u, m, o));
            float e[4], sum = 0.f;
            #pragma unroll
            for (int s = 0; s < 4; s++) { e[s] = al[s] ? __expf(vals[s] - m) : 0.f; sum += e[s]; }
            #pragma unroll
            for (int o = 16; o; o >>= 1) sum += __shfl_xor_sync(~0u, sum, o);
            float inv = 1.f / sum;
            #pragma unroll
            for (int s = 0; s < 4; s++) Ps[r * PS_STRIDE + lane + 32 * s] = e[s] * inv;
        }
    }
    __syncthreads();

    // ---- O = P @ V2 with per-warp causal j-bound ----
    u64 o2[8][2];
    #pragma unroll
    for (int i = 0; i < 8; i++) { o2[i][0] = 0ull; o2[i][1] = 0ull; }
    int jmax = 72 + 8 * rg;   // 72,80,...,128
    #pragma unroll 4
    for (int j = 0; j < jmax; j += 2) {
        u64 a2[8], b2[2];
        #pragma unroll
        for (int i = 0; i < 8; i++) a2[i] = *(const u64*)&Ps[(rg * 8 + i) * PS_STRIDE + j];
        b2[0] = *(const u64*)&V2T[(cg +  0) * PS_STRIDE + j];
        b2[1] = *(const u64*)&V2T[(cg + 32) * PS_STRIDE + j];
        #pragma unroll
        for (int i = 0; i < 8; i++) {
            fma2(o2[i][0], a2[i], b2[0]);
            fma2(o2[i][1], a2[i], b2[1]);
        }
    }

    float* og = out + (size_t)f * T_ * DH;
    #pragma unroll
    for (int i = 0; i < 8; i++) {
        int r  = rg * 8 + i;
        int tt = u * BSZ + r;
        int dst = rot ? ((tt + 63) & (T_ - 1)) : tt;
        og[dst * DH + cg]      = f2sum(o2[i][0]);
        og[dst * DH + cg + 32] = f2sum(o2[i][1]);
    }
}

// ---------------------------------------------------------------------------
extern "C" void kernel_launch(void* const* d_in, const int* in_sizes, int n_in,
                              void* d_out, int out_size) {
    const float* q  = (const float*)d_in[0];
    const float* k  = (const float*)d_in[1];
    const float* v  = (const float*)d_in[2];
    const float* W  = (const float*)d_in[3];
    const float* nk = (const float*)d_in[4];
    const float* nv = (const float*)d_in[5];
    float* out = (float*)d_out;

    k_bucket_sums<<<dim3(BUCKETS, BH), 256>>>(k);
    k_prefix<<<BH, 256>>>();

    const size_t smem_r = (size_t)((64 + 128) * RW_STR) * sizeof(float);   // 99840 B
    cudaFuncSetAttribute(k_route, cudaFuncAttributeMaxDynamicSharedMemorySize, (int)smem_r);
    k_route<<<dim3(2, BH), 256, smem_r>>>(W);

    const size_t smem = (size_t)((64 + 128) * QS_STRIDE + 64 * PS_STRIDE) * sizeof(float); // 83968 B
    cudaFuncSetAttribute(k_attn, cudaFuncAttributeMaxDynamicSharedMemorySize, (int)smem);
    k_attn<<<dim3(BUCKETS, BH), 256, smem>>>(q, k, v, nk, nv, out);
}

// round 16
// speedup vs baseline: 1.0714x; 1.0714x over previous
#include <cuda_runtime.h>
#include <math_constants.h>

#define B_      8
#define H_      8
#define T_      8192
#define DH      64
#define BUCKETS 128
#define BSZ     64
#define BH      64
#define HH      4

// scratch (device globals; no allocation allowed)
__device__ float g_bucket_sum[BH * BUCKETS * DH];   // 2 MB
__device__ float g_feat[BH * BUCKETS * 2 * DH];     // 4 MB
__device__ int   g_ridx[BH * BUCKETS];              // (unused after fusion; kept)
__device__ float g_rw[BH * BUCKETS];

typedef unsigned long long u64;

__device__ __forceinline__ void fma2(u64 &d, u64 a, u64 b) {
    asm("fma.rn.f32x2 %0, %1, %2, %0;" : "+l"(d) : "l"(a), "l"(b));
}
__device__ __forceinline__ float f2sum(u64 v) {
    return __uint_as_float((unsigned)v) + __uint_as_float((unsigned)(v >> 32));
}

// ---------------------------------------------------------------------------
// Kernel 1: per-bucket sums of rotated K + first-token capture (exact R8)
__global__ void k_bucket_sums(const float* __restrict__ k) {
    int u = blockIdx.x, f = blockIdx.y;
    int h = f & 7; bool rot = (h >= HH);
    const float* kg = k + (size_t)f * T_ * DH;
    __shared__ float4 red[16][17];
    int cgrp = threadIdx.x & 15;
    int c4 = cgrp * 4;
    int rp = threadIdx.x >> 4;

    float4 s = {0.f, 0.f, 0.f, 0.f};
    #pragma unroll
    for (int st = 0; st < 4; st++) {
        int i = rp + 16 * st;
        int tt = u * BSZ + i;
        int src = rot ? ((tt + 63) & (T_ - 1)) : tt;
        float4 vv = *(const float4*)(kg + src * DH + c4);
        s.x += vv.x; s.y += vv.y; s.z += vv.z; s.w += vv.w;
        if (rp == 0 && st == 0)
            *(float4*)&g_feat[(f * BUCKETS + u) * 128 + 64 + c4] = vv;
    }
    red[rp][cgrp] = s;
    __syncthreads();
    if (rp == 0) {
        float4 acc = red[0][cgrp];
        #pragma unroll
        for (int r = 1; r < 16; r++) {
            float4 t2 = red[r][cgrp];
            acc.x += t2.x; acc.y += t2.y; acc.z += t2.z; acc.w += t2.w;
        }
        *(float4*)&g_bucket_sum[(f * BUCKETS + u) * DH + c4] = acc;
    }
}

// ---------------------------------------------------------------------------
// Kernel 2: smem Hillis–Steele scan over buckets -> cumavg feature (exact R8)
__global__ void k_prefix() {
    __shared__ float s[BUCKETS * DH];   // 32 KB
    int f = blockIdx.x, tid = threadIdx.x;
    const float* src = g_bucket_sum + (size_t)f * BUCKETS * DH;

    for (int i = tid; i < BUCKETS * DH / 4; i += 256)
        ((float4*)s)[i] = ((const float4*)src)[i];
    __syncthreads();

    #pragma unroll
    for (int off = 1; off < BUCKETS; off <<= 1) {
        float vals[32];
        #pragma unroll
        for (int t = 0; t < 32; t++) {
            int e = tid + 256 * t;
            int u = e >> 6;
            vals[t] = (u >= off) ? s[e - off * DH] : 0.f;
        }
        __syncthreads();
        #pragma unroll
        for (int t = 0; t < 32; t++) s[tid + 256 * t] += vals[t];
        __syncthreads();
    }

    for (int e = tid; e < BUCKETS * DH; e += 256) {
        int u = e >> 6, d = e & 63;
        float excl = s[e] - src[e];
        float first = g_feat[(f * BUCKETS + u) * 128 + 64 + d];
        g_feat[(f * BUCKETS + u) * 128 + d] = (excl + first) / (float)(u * BSZ + 1);
    }
}

// ---------------------------------------------------------------------------
// Kernel 3: fused attention tile — R8 core + inlined per-block routing
// (routing GEMV/softmax/top-1 copied verbatim from R8's k_route; its gmem
//  latency hides under the own-half tile loads)
#define QS_STRIDE  66
#define PS_STRIDE  130
__global__ void __launch_bounds__(256, 2) k_attn(
    const float* __restrict__ q, const float* __restrict__ k, const float* __restrict__ v,
    const float* __restrict__ W,
    const float* __restrict__ nullk, const float* __restrict__ nullv,
    float* __restrict__ out)
{
    extern __shared__ float sm[];
    float* Qs  = sm;                                   // [64][66]
    float* K2s = sm + 64 * QS_STRIDE;                  // [128][66]
    float* Ps  = sm;                                   // [64][130] overlay (after sync)
    float* V2T = sm + (64 + 128) * QS_STRIDE;          // [64][130]  V2T[c][j]
    __shared__ float xs[128];
    __shared__ float ls[132];
    __shared__ float s_w;
    __shared__ int   s_ridx;

    int u = blockIdx.x, f = blockIdx.y, tid = threadIdx.x;
    int h = f & 7; bool rot = (h >= HH);
    const float* qg = q + (size_t)f * T_ * DH;
    const float* kg = k + (size_t)f * T_ * DH;
    const float* vg = v + (size_t)f * T_ * DH;

    // ---- routing feature load (issued first; latency hidden by own loads) --
    if (tid < 128) xs[tid] = g_feat[(f * BUCKETS + u) * 128 + tid];

    // ---- own-half loads: Q, K2 own rows, V2T own cols (independent of route)
    for (int idx = tid; idx < 64 * 16; idx += 256) {
        int row = idx >> 4, c4 = (idx & 15) << 2;
        int tt  = u * BSZ + row;
        int src = rot ? ((tt + 63) & (T_ - 1)) : tt;
        float4 qv = *(const float4*)(qg + src * DH + c4);
        *(float2*)&Qs[row * QS_STRIDE + c4]     = make_float2(qv.x, qv.y);
        *(float2*)&Qs[row * QS_STRIDE + c4 + 2] = make_float2(qv.z, qv.w);
        float4 kv = *(const float4*)(kg + src * DH + c4);
        *(float2*)&K2s[(64 + row) * QS_STRIDE + c4]     = make_float2(kv.x, kv.y);
        *(float2*)&K2s[(64 + row) * QS_STRIDE + c4 + 2] = make_float2(kv.z, kv.w);
        float4 vv = *(const float4*)(vg + src * DH + c4);
        V2T[(c4 + 0) * PS_STRIDE + 64 + row] = vv.x;
        V2T[(c4 + 1) * PS_STRIDE + 64 + row] = vv.y;
        V2T[(c4 + 2) * PS_STRIDE + 64 + row] = vv.z;
        V2T[(c4 + 3) * PS_STRIDE + 64 + row] = vv.w;
    }
    __syncthreads();

    // ---- routing GEMV + leaky_relu (verbatim R8 k_route) ----
    if (tid <= u) {
        float acc = 0.f;
        const float* wp = W + h * 128 * 129 + tid;
        #pragma unroll 8
        for (int d = 0; d < 128; d++) acc += xs[d] * wp[d * 129];
        ls[tid] = acc > 0.f ? acc : 0.01f * acc;
    }
    __syncthreads();
    if (tid < 32) {
        float m = -CUDART_INF_F;
        for (int c = tid; c <= u; c += 32) m = fmaxf(m, ls[c]);
        #pragma unroll
        for (int o = 16; o; o >>= 1) m = fmaxf(m, __shfl_xor_sync(~0u, m, o));
        float sum = 0.f, best = -CUDART_INF_F; int bi = 0x7fffffff;
        for (int c = tid; c <= u; c += 32) {
            float e = __expf(ls[c] - m);
            sum += e;
            if (c < u && ls[c] > best) { best = ls[c]; bi = c; }
        }
        #pragma unroll
        for (int o = 16; o; o >>= 1) {
            sum += __shfl_xor_sync(~0u, sum, o);
            float ob = __shfl_xor_sync(~0u, best, o);
            int   oi = __shfl_xor_sync(~0u, bi, o);
            if (ob > best || (ob == best && oi < bi)) { best = ob; bi = oi; }
        }
        if (tid == 0) {
            if (u == 0) { s_ridx = 0; s_w = 0.f; }
            else {
                s_ridx = bi;                      // 0 = null bucket
                s_w    = __expf(best - m) / sum;  // softmax weight
            }
        }
    }
    __syncthreads();
    int   ridx = s_ridx;
    float w    = s_w;

    // ---- routed-half loads: K2 routed rows, V2T routed cols ----
    for (int idx = tid; idx < 64 * 16; idx += 256) {
        int row = idx >> 4, c4 = (idx & 15) << 2;
        float4 rk, rv;
        if (ridx == 0) {
            rk = *(const float4*)(nullk + h * DH + c4);
            rv = *(const float4*)(nullv + h * DH + c4);
        } else {
            int st = (ridx - 1) * BSZ + row;
            int s2 = rot ? ((st + 63) & (T_ - 1)) : st;
            rk = *(const float4*)(kg + s2 * DH + c4);
            rv = *(const float4*)(vg + s2 * DH + c4);
        }
        rk.x *= w; rk.y *= w; rk.z *= w; rk.w *= w;
        *(float2*)&K2s[row * QS_STRIDE + c4]     = make_float2(rk.x, rk.y);
        *(float2*)&K2s[row * QS_STRIDE + c4 + 2] = make_float2(rk.z, rk.w);
        V2T[(c4 + 0) * PS_STRIDE + row] = rv.x * w;
        V2T[(c4 + 1) * PS_STRIDE + row] = rv.y * w;
        V2T[(c4 + 2) * PS_STRIDE + row] = rv.z * w;
        V2T[(c4 + 3) * PS_STRIDE + row] = rv.w * w;
    }
    __syncthreads();

    // ---- S = Q @ K2^T with causal col-group skip (exact R8) ----
    int rg = tid >> 5, cg = tid & 31;
    u64 acc[8][4];
    #pragma unroll
    for (int i = 0; i < 8; i++)
        #pragma unroll
        for (int j = 0; j < 4; j++) acc[i][j] = 0ull;

    if (rg >= 4) {
        #pragma unroll 2
        for (int kk = 0; kk < 64; kk += 2) {
            u64 a2[8], b2[4];
            #pragma unroll
            for (int i = 0; i < 8; i++) a2[i] = *(const u64*)&Qs[(rg * 8 + i) * QS_STRIDE + kk];
            #pragma unroll
            for (int j = 0; j < 4; j++) b2[j] = *(const u64*)&K2s[(cg + 32 * j) * QS_STRIDE + kk];
            #pragma unroll
            for (int i = 0; i < 8; i++)
                #pragma unroll
                for (int j = 0; j < 4; j++) fma2(acc[i][j], a2[i], b2[j]);
        }
    } else {
        #pragma unroll 2
        for (int kk = 0; kk < 64; kk += 2) {
            u64 a2[8], b2[3];
            #pragma unroll
            for (int i = 0; i < 8; i++) a2[i] = *(const u64*)&Qs[(rg * 8 + i) * QS_STRIDE + kk];
            #pragma unroll
            for (int j = 0; j < 3; j++) b2[j] = *(const u64*)&K2s[(cg + 32 * j) * QS_STRIDE + kk];
            #pragma unroll
            for (int i = 0; i < 8; i++)
                #pragma unroll
                for (int j = 0; j < 3; j++) fma2(acc[i][j], a2[i], b2[j]);
        }
    }
    __syncthreads();  // all Qs/K2s reads done; Ps overlays them

    {
        const float scale = 0.044194173824159216f;  // 512^-0.5
        #pragma unroll
        for (int i = 0; i < 8; i++)
            #pragma unroll
            for (int j = 0; j < 3; j++)
                Ps[(rg * 8 + i) * PS_STRIDE + (cg + 32 * j)] = f2sum(acc[i][j]) * scale;
        if (rg >= 4) {
            #pragma unroll
            for (int i = 0; i < 8; i++)
                Ps[(rg * 8 + i) * PS_STRIDE + (cg + 96)] = f2sum(acc[i][3]) * scale;
        }
    }
    __syncthreads();

    // ---- masked softmax: warp per 8 rows (exact R8) ----
    {
        int warp = tid >> 5, lane = tid & 31;
        for (int rr = 0; rr < 8; rr++) {
            int r = warp * 8 + rr;
            bool special = rot && (u == BUCKETS - 1) && (r >= 1);
            float vals[4]; bool al[4];
            #pragma unroll
            for (int s = 0; s < 4; s++) {
                int j = lane + 32 * s;
                vals[s] = Ps[r * PS_STRIDE + j];
                bool a = (j < 64) ? true : ((j - 64) <= r);
                if (special && j <= 64) a = false;
                al[s] = a;
            }
            float m = -CUDART_INF_F;
            #pragma unroll
            for (int s = 0; s < 4; s++) if (al[s]) m = fmaxf(m, vals[s]);
            #pragma unroll
            for (int o = 16; o; o >>= 1) m = fmaxf(m, __shfl_xor_sync(~0u, m, o));
            float e[4], sum = 0.f;
            #pragma unroll
            for (int s = 0; s < 4; s++) { e[s] = al[s] ? __expf(vals[s] - m) : 0.f; sum += e[s]; }
            #pragma unroll
            for (int o = 16; o; o >>= 1) sum += __shfl_xor_sync(~0u, sum, o);
            float inv = 1.f / sum;
            #pragma unroll
            for (int s = 0; s < 4; s++) Ps[r * PS_STRIDE + lane + 32 * s] = e[s] * inv;
        }
    }
    __syncthreads();

    // ---- O = P @ V2 with per-warp causal j-bound (exact R8) ----
    u64 o2[8][2];
    #pragma unroll
    for (int i = 0; i < 8; i++) { o2[i][0] = 0ull; o2[i][1] = 0ull; }
    int jmax = 72 + 8 * rg;   // 72,80,...,128
    #pragma unroll 4
    for (int j = 0; j < jmax; j += 2) {
        u64 a2[8], b2[2];
        #pragma unroll
        for (int i = 0; i < 8; i++) a2[i] = *(const u64*)&Ps[(rg * 8 + i) * PS_STRIDE + j];
        b2[0] = *(const u64*)&V2T[(cg +  0) * PS_STRIDE + j];
        b2[1] = *(const u64*)&V2T[(cg + 32) * PS_STRIDE + j];
        #pragma unroll
        for (int i = 0; i < 8; i++) {
            fma2(o2[i][0], a2[i], b2[0]);
            fma2(o2[i][1], a2[i], b2[1]);
        }
    }

    float* og = out + (size_t)f * T_ * DH;
    #pragma unroll
    for (int i = 0; i < 8; i++) {
        int r  = rg * 8 + i;
        int tt = u * BSZ + r;
        int dst = rot ? ((tt + 63) & (T_ - 1)) : tt;
        og[dst * DH + cg]      = f2sum(o2[i][0]);
        og[dst * DH + cg + 32] = f2sum(o2[i][1]);
    }
}

// ---------------------------------------------------------------------------
extern "C" void kernel_launch(void* const* d_in, const int* in_sizes, int n_in,
                              void* d_out, int out_size) {
    const float* q  = (const float*)d_in[0];
    const float* k  = (const float*)d_in[1];
    const float* v  = (const float*)d_in[2];
    const float* W  = (const float*)d_in[3];
    const float* nk = (const float*)d_in[4];
    const float* nv = (const float*)d_in[5];
    float* out = (float*)d_out;

    k_bucket_sums<<<dim3(BUCKETS, BH), 256>>>(k);
    k_prefix<<<BH, 256>>>();

    const size_t smem = (size_t)((64 + 128) * QS_STRIDE + 64 * PS_STRIDE) * sizeof(float); // 83968 B
    cudaFuncSetAttribute(k_attn, cudaFuncAttributeMaxDynamicSharedMemorySize, (int)smem);
    k_attn<<<dim3(BUCKETS, BH), 256, smem>>>(q, k, v, W, nk, nv, out);
}

// round 17
// speedup vs baseline: 1.1990x; 1.1191x over previous
#include <cuda_runtime.h>
#include <math_constants.h>

#define B_      8
#define H_      8
#define T_      8192
#define DH      64
#define BUCKETS 128
#define BSZ     64
#define BH      64
#define HH      4

// scratch (device globals; no allocation allowed)
__device__ float g_bucket_sum[BH * BUCKETS * DH];   // 2 MB
__device__ float g_feat[BH * BUCKETS * 2 * DH];     // 4 MB
__device__ int   g_ridx[BH * BUCKETS];
__device__ float g_rw[BH * BUCKETS];

typedef unsigned long long u64;

__device__ __forceinline__ void fma2(u64 &d, u64 a, u64 b) {
    asm("fma.rn.f32x2 %0, %1, %2, %0;" : "+l"(d) : "l"(a), "l"(b));
}
__device__ __forceinline__ float f2sum(u64 v) {
    return __uint_as_float((unsigned)v) + __uint_as_float((unsigned)(v >> 32));
}

// ---------------------------------------------------------------------------
// Kernel 1: per-bucket sums of rotated K + first-token capture (exact R8)
__global__ void k_bucket_sums(const float* __restrict__ k) {
    int u = blockIdx.x, f = blockIdx.y;
    int h = f & 7; bool rot = (h >= HH);
    const float* kg = k + (size_t)f * T_ * DH;
    __shared__ float4 red[16][17];
    int cgrp = threadIdx.x & 15;
    int c4 = cgrp * 4;
    int rp = threadIdx.x >> 4;

    float4 s = {0.f, 0.f, 0.f, 0.f};
    #pragma unroll
    for (int st = 0; st < 4; st++) {
        int i = rp + 16 * st;
        int tt = u * BSZ + i;
        int src = rot ? ((tt + 63) & (T_ - 1)) : tt;
        float4 vv = *(const float4*)(kg + src * DH + c4);
        s.x += vv.x; s.y += vv.y; s.z += vv.z; s.w += vv.w;
        if (rp == 0 && st == 0)
            *(float4*)&g_feat[(f * BUCKETS + u) * 128 + 64 + c4] = vv;
    }
    red[rp][cgrp] = s;
    __syncthreads();
    if (rp == 0) {
        float4 acc = red[0][cgrp];
        #pragma unroll
        for (int r = 1; r < 16; r++) {
            float4 t2 = red[r][cgrp];
            acc.x += t2.x; acc.y += t2.y; acc.z += t2.z; acc.w += t2.w;
        }
        *(float4*)&g_bucket_sum[(f * BUCKETS + u) * DH + c4] = acc;
    }
}

// ---------------------------------------------------------------------------
// Kernel 2: smem Hillis–Steele scan over buckets -> cumavg feature (exact R8)
__global__ void k_prefix() {
    __shared__ float s[BUCKETS * DH];   // 32 KB
    int f = blockIdx.x, tid = threadIdx.x;
    const float* src = g_bucket_sum + (size_t)f * BUCKETS * DH;

    for (int i = tid; i < BUCKETS * DH / 4; i += 256)
        ((float4*)s)[i] = ((const float4*)src)[i];
    __syncthreads();

    #pragma unroll
    for (int off = 1; off < BUCKETS; off <<= 1) {
        float vals[32];
        #pragma unroll
        for (int t = 0; t < 32; t++) {
            int e = tid + 256 * t;
            int u = e >> 6;
            vals[t] = (u >= off) ? s[e - off * DH] : 0.f;
        }
        __syncthreads();
        #pragma unroll
        for (int t = 0; t < 32; t++) s[tid + 256 * t] += vals[t];
        __syncthreads();
    }

    for (int e = tid; e < BUCKETS * DH; e += 256) {
        int u = e >> 6, d = e & 63;
        float excl = s[e] - src[e];
        float first = g_feat[(f * BUCKETS + u) * 128 + 64 + d];
        g_feat[(f * BUCKETS + u) * 128 + d] = (excl + first) / (float)(u * BSZ + 1);
    }
}

// ---------------------------------------------------------------------------
// Kernel 3: routing v4 — one block per f; stage X[f] + W[h] (UNtransposed)
// in 128KB dyn smem; d-outer GEMV, warp-uniform causal group count,
// per-column arithmetic identical to naive route (ascending d, single acc).
template<int G>
__device__ __forceinline__ void route_gemv(
    const float* __restrict__ Xs, const float* __restrict__ Ws,
    int lane, int r0, float acc[16][4])
{
    #pragma unroll 2
    for (int d = 0; d < 128; d++) {
        float wv[G];
        #pragma unroll
        for (int j = 0; j < G; j++) wv[j] = Ws[d * 128 + lane + 32 * j];
        #pragma unroll
        for (int ui = 0; ui < 16; ui++) {
            float a = Xs[(r0 + ui) * 128 + d];   // warp broadcast
            #pragma unroll
            for (int j = 0; j < G; j++) acc[ui][j] += a * wv[j];
        }
    }
}

__global__ void __launch_bounds__(256) k_route(const float* __restrict__ W) {
    extern __shared__ float rsm[];
    float* Xs = rsm;              // [128][128]
    float* Ws = rsm + 128 * 128;  // [128][128]  Ws[d][c] (col 128 never needed)
    int f = blockIdx.x, tid = threadIdx.x;
    int h = f & 7;

    // stage X[f] (float4, coalesced)
    for (int idx = tid; idx < 128 * 32; idx += 256) {
        int u = idx >> 5, d4 = (idx & 31) << 2;
        *(float4*)&Xs[u * 128 + d4] =
            *(const float4*)&g_feat[(f * BUCKETS + u) * 128 + d4];
    }
    // stage W[h] rows (scalar, coalesced along c; row stride 129 in gmem)
    const float* wh = W + h * 128 * 129;
    for (int idx = tid; idx < 128 * 128; idx += 256) {
        int d = idx >> 7, c = idx & 127;
        Ws[d * 128 + c] = wh[d * 129 + c];
    }
    __syncthreads();

    int wrp = tid >> 5, lane = tid & 31;
    int r0 = wrp * 16;                 // this warp's 16 buckets
    int g = (wrp >> 1) + 1;            // uniform col groups needed (1..4)

    float acc[16][4];
    #pragma unroll
    for (int ui = 0; ui < 16; ui++)
        #pragma unroll
        for (int j = 0; j < 4; j++) acc[ui][j] = 0.f;

    switch (g) {
        case 1: route_gemv<1>(Xs, Ws, lane, r0, acc); break;
        case 2: route_gemv<2>(Xs, Ws, lane, r0, acc); break;
        case 3: route_gemv<3>(Xs, Ws, lane, r0, acc); break;
        default: route_gemv<4>(Xs, Ws, lane, r0, acc); break;
    }

    // per-bucket: leaky_relu, masked softmax over c<=u, top-1 over c<u
    #pragma unroll 1
    for (int ui = 0; ui < 16; ui++) {
        int u = r0 + ui;
        float vals[4];
        float m = -CUDART_INF_F;
        #pragma unroll
        for (int j = 0; j < 4; j++) {
            int c = lane + 32 * j;
            float v = acc[ui][j];
            v = v > 0.f ? v : 0.01f * v;          // leaky_relu
            vals[j] = v;
            if (j < g && c <= u) m = fmaxf(m, v);
        }
        #pragma unroll
        for (int o = 16; o; o >>= 1) m = fmaxf(m, __shfl_xor_sync(~0u, m, o));
        float sum = 0.f, best = -CUDART_INF_F; int bi = 0x7fffffff;
        #pragma unroll
        for (int j = 0; j < 4; j++) {
            int c = lane + 32 * j;
            if (j < g && c <= u) sum += __expf(vals[j] - m);
            if (j < g && c <  u && vals[j] > best) { best = vals[j]; bi = c; }
        }
        #pragma unroll
        for (int o = 16; o; o >>= 1) {
            sum += __shfl_xor_sync(~0u, sum, o);
            float ob = __shfl_xor_sync(~0u, best, o);
            int   oi = __shfl_xor_sync(~0u, bi, o);
            if (ob > best || (ob == best && oi < bi)) { best = ob; bi = oi; }
        }
        if (lane == 0) {
            if (u == 0) { g_ridx[f * BUCKETS] = 0; g_rw[f * BUCKETS] = 0.f; }
            else {
                g_ridx[f * BUCKETS + u] = bi;                      // 0 = null bucket
                g_rw[f * BUCKETS + u]   = __expf(best - m) / sum;  // softmax weight
            }
        }
    }
}

// ---------------------------------------------------------------------------
// Kernel 4: fused attention tile (exact R8 version — best known: 463.7us)
#define QS_STRIDE  66
#define PS_STRIDE  130
__global__ void __launch_bounds__(256, 2) k_attn(
    const float* __restrict__ q, const float* __restrict__ k, const float* __restrict__ v,
    const float* __restrict__ nullk, const float* __restrict__ nullv,
    float* __restrict__ out)
{
    extern __shared__ float sm[];
    float* Qs  = sm;                                   // [64][66]
    float* K2s = sm + 64 * QS_STRIDE;                  // [128][66]
    float* Ps  = sm;                                   // [64][130] overlay (after sync)
    float* V2T = sm + (64 + 128) * QS_STRIDE;          // [64][130]  V2T[c][j]

    int u = blockIdx.x, f = blockIdx.y, tid = threadIdx.x;
    int h = f & 7; bool rot = (h >= HH);
    const float* qg = q + (size_t)f * T_ * DH;
    const float* kg = k + (size_t)f * T_ * DH;
    const float* vg = v + (size_t)f * T_ * DH;
    int   ridx = g_ridx[f * BUCKETS + u];
    float w    = g_rw[f * BUCKETS + u];

    // ---- load Q, K2 (routed|own), V2T (routed|own transposed) ----
    for (int idx = tid; idx < 64 * 16; idx += 256) {
        int row = idx >> 4, c4 = (idx & 15) << 2;
        int tt  = u * BSZ + row;
        int src = rot ? ((tt + 63) & (T_ - 1)) : tt;
        float4 qv = *(const float4*)(qg + src * DH + c4);
        *(float2*)&Qs[row * QS_STRIDE + c4]     = make_float2(qv.x, qv.y);
        *(float2*)&Qs[row * QS_STRIDE + c4 + 2] = make_float2(qv.z, qv.w);
        float4 kv = *(const float4*)(kg + src * DH + c4);
        *(float2*)&K2s[(64 + row) * QS_STRIDE + c4]     = make_float2(kv.x, kv.y);
        *(float2*)&K2s[(64 + row) * QS_STRIDE + c4 + 2] = make_float2(kv.z, kv.w);
        float4 vv = *(const float4*)(vg + src * DH + c4);
        V2T[(c4 + 0) * PS_STRIDE + 64 + row] = vv.x;
        V2T[(c4 + 1) * PS_STRIDE + 64 + row] = vv.y;
        V2T[(c4 + 2) * PS_STRIDE + 64 + row] = vv.z;
        V2T[(c4 + 3) * PS_STRIDE + 64 + row] = vv.w;
        float4 rk, rv;
        if (ridx == 0) {
            rk = *(const float4*)(nullk + h * DH + c4);
            rv = *(const float4*)(nullv + h * DH + c4);
        } else {
            int st = (ridx - 1) * BSZ + row;
            int s2 = rot ? ((st + 63) & (T_ - 1)) : st;
            rk = *(const float4*)(kg + s2 * DH + c4);
            rv = *(const float4*)(vg + s2 * DH + c4);
        }
        rk.x *= w; rk.y *= w; rk.z *= w; rk.w *= w;
        *(float2*)&K2s[row * QS_STRIDE + c4]     = make_float2(rk.x, rk.y);
        *(float2*)&K2s[row * QS_STRIDE + c4 + 2] = make_float2(rk.z, rk.w);
        V2T[(c4 + 0) * PS_STRIDE + row] = rv.x * w;
        V2T[(c4 + 1) * PS_STRIDE + row] = rv.y * w;
        V2T[(c4 + 2) * PS_STRIDE + row] = rv.z * w;
        V2T[(c4 + 3) * PS_STRIDE + row] = rv.w * w;
    }
    __syncthreads();

    // ---- S = Q @ K2^T with causal col-group skip ----
    int rg = tid >> 5, cg = tid & 31;
    u64 acc[8][4];
    #pragma unroll
    for (int i = 0; i < 8; i++)
        #pragma unroll
        for (int j = 0; j < 4; j++) acc[i][j] = 0ull;

    if (rg >= 4) {
        #pragma unroll 2
        for (int kk = 0; kk < 64; kk += 2) {
            u64 a2[8], b2[4];
            #pragma unroll
            for (int i = 0; i < 8; i++) a2[i] = *(const u64*)&Qs[(rg * 8 + i) * QS_STRIDE + kk];
            #pragma unroll
            for (int j = 0; j < 4; j++) b2[j] = *(const u64*)&K2s[(cg + 32 * j) * QS_STRIDE + kk];
            #pragma unroll
            for (int i = 0; i < 8; i++)
                #pragma unroll
                for (int j = 0; j < 4; j++) fma2(acc[i][j], a2[i], b2[j]);
        }
    } else {
        #pragma unroll 2
        for (int kk = 0; kk < 64; kk += 2) {
            u64 a2[8], b2[3];
            #pragma unroll
            for (int i = 0; i < 8; i++) a2[i] = *(const u64*)&Qs[(rg * 8 + i) * QS_STRIDE + kk];
            #pragma unroll
            for (int j = 0; j < 3; j++) b2[j] = *(const u64*)&K2s[(cg + 32 * j) * QS_STRIDE + kk];
            #pragma unroll
            for (int i = 0; i < 8; i++)
                #pragma unroll
                for (int j = 0; j < 3; j++) fma2(acc[i][j], a2[i], b2[j]);
        }
    }
    __syncthreads();  // all Qs/K2s reads done; Ps overlays them

    {
        const float scale = 0.044194173824159216f;  // 512^-0.5
        #pragma unroll
        for (int i = 0; i < 8; i++)
            #pragma unroll
            for (int j = 0; j < 3; j++)
                Ps[(rg * 8 + i) * PS_STRIDE + (cg + 32 * j)] = f2sum(acc[i][j]) * scale;
        if (rg >= 4) {
            #pragma unroll
            for (int i = 0; i < 8; i++)
                Ps[(rg * 8 + i) * PS_STRIDE + (cg + 96)] = f2sum(acc[i][3]) * scale;
        }
    }
    __syncthreads();

    // ---- masked softmax: warp per 8 rows ----
    {
        int warp = tid >> 5, lane = tid & 31;
        for (int rr = 0; rr < 8; rr++) {
            int r = warp * 8 + rr;
            bool special = rot && (u == BUCKETS - 1) && (r >= 1);
            float vals[4]; bool al[4];
            #pragma unroll
            for (int s = 0; s < 4; s++) {
                int j = lane + 32 * s;
                vals[s] = Ps[r * PS_STRIDE + j];
                bool a = (j < 64) ? true : ((j - 64) <= r);
                if (special && j <= 64) a = false;
                al[s] = a;
            }
            float m = -CUDART_INF_F;
            #pragma unroll
            for (int s = 0; s < 4; s++) if (al[s]) m = fmaxf(m, vals[s]);
            #pragma unroll
            for (int o = 16; o; o >>= 1) m = fmaxf(m, __shfl_xor_sync(~0u, m, o));
            float e[4], sum = 0.f;
            #pragma unroll
            for (int s = 0; s < 4; s++) { e[s] = al[s] ? __expf(vals[s] - m) : 0.f; sum += e[s]; }
            #pragma unroll
            for (int o = 16; o; o >>= 1) sum += __shfl_xor_sync(~0u, sum, o);
            float inv = 1.f / sum;
            #pragma unroll
            for (int s = 0; s < 4; s++) Ps[r * PS_STRIDE + lane + 32 * s] = e[s] * inv;
        }
    }
    __syncthreads();

    // ---- O = P @ V2 with per-warp causal j-bound ----
    u64 o2[8][2];
    #pragma unroll
    for (int i = 0; i < 8; i++) { o2[i][0] = 0ull; o2[i][1] = 0ull; }
    int jmax = 72 + 8 * rg;   // 72,80,...,128
    #pragma unroll 4
    for (int j = 0; j < jmax; j += 2) {
        u64 a2[8], b2[2];
        #pragma unroll
        for (int i = 0; i < 8; i++) a2[i] = *(const u64*)&Ps[(rg * 8 + i) * PS_STRIDE + j];
        b2[0] = *(const u64*)&V2T[(cg +  0) * PS_STRIDE + j];
        b2[1] = *(const u64*)&V2T[(cg + 32) * PS_STRIDE + j];
        #pragma unroll
        for (int i = 0; i < 8; i++) {
            fma2(o2[i][0], a2[i], b2[0]);
            fma2(o2[i][1], a2[i], b2[1]);
        }
    }

    float* og = out + (size_t)f * T_ * DH;
    #pragma unroll
    for (int i = 0; i < 8; i++) {
        int r  = rg * 8 + i;
        int tt = u * BSZ + r;
        int dst = rot ? ((tt + 63) & (T_ - 1)) : tt;
        og[dst * DH + cg]      = f2sum(o2[i][0]);
        og[dst * DH + cg + 32] = f2sum(o2[i][1]);
    }
}

// ---------------------------------------------------------------------------
extern "C" void kernel_launch(void* const* d_in, const int* in_sizes, int n_in,
                              void* d_out, int out_size) {
    const float* q  = (const float*)d_in[0];
    const float* k  = (const float*)d_in[1];
    const float* v  = (const float*)d_in[2];
    const float* W  = (const float*)d_in[3];
    const float* nk = (const float*)d_in[4];
    const float* nv = (const float*)d_in[5];
    float* out = (float*)d_out;

    k_bucket_sums<<<dim3(BUCKETS, BH), 256>>>(k);
    k_prefix<<<BH, 256>>>();

    const size_t smem_r = (size_t)(2 * 128 * 128) * sizeof(float);   // 131072 B
    cudaFuncSetAttribute(k_route, cudaFuncAttributeMaxDynamicSharedMemorySize, (int)smem_r);
    k_route<<<BH, 256, smem_r>>>(W);

    const size_t smem = (size_t)((64 + 128) * QS_STRIDE + 64 * PS_STRIDE) * sizeof(float); // 83968 B
    cudaFuncSetAttribute(k_attn, cudaFuncAttributeMaxDynamicSharedMemorySize, (int)smem);
    k_attn<<<dim3(BUCKETS, BH), 256, smem>>>(q, k, v, nk, nv, out);
}